// round 8
// baseline (speedup 1.0000x reference)
#include <cuda_runtime.h>

#define BB 4
#define LQ 512
#define LK 512
#define EE 128
#define DD 256
#define TL 8

// Scratch for projected q/k (allocation-free: device globals).
__device__ float g_qproj[BB * LQ * EE];
__device__ float g_kproj[BB * LK * EE];

__device__ __forceinline__ float tanh_fast(float x) {
    float y;
    asm("tanh.approx.f32 %0, %1;" : "=f"(y) : "f"(x));
    return y;
}

// ---------------------------------------------------------------------------
// Projection GEMM: O[2048,128] = X[2048,256] @ W[256,128]
// blockIdx.z = 0 -> (query, Wc1, g_qproj); 1 -> (key, Wc2, g_kproj)
// BM=32, BN=128, BK=32; 256 threads; 4x4 outputs per thread.
// ---------------------------------------------------------------------------
__global__ __launch_bounds__(256) void proj_kernel(
    const float* __restrict__ query, const float* __restrict__ key,
    const float* __restrict__ Wc1, const float* __restrict__ Wc2)
{
    const float* X = (blockIdx.z == 0) ? query : key;
    const float* W = (blockIdx.z == 0) ? Wc1 : Wc2;
    float* O       = (blockIdx.z == 0) ? g_qproj : g_kproj;

    __shared__ float As[32][36];   // [k][m], pad 36 -> 16B-aligned rows, conflict-free
    __shared__ float Bs[32][128];  // [k][n]

    const int tid = threadIdx.x;
    const int m0  = blockIdx.x * 32;
    const int tx  = tid & 31;   // n-group (4 cols each)
    const int ty  = tid >> 5;   // m-group (4 rows each)

    const int lr = tid >> 3;          // 0..31 : m row for X load
    const int lc = (tid & 7) << 2;    // 0..28 : k col (float4)

    float acc[4][4] = {};

    for (int k0 = 0; k0 < DD; k0 += 32) {
        // X tile (coalesced float4), stored transposed into As[k][m]
        float4 x4 = *(const float4*)(X + (size_t)(m0 + lr) * DD + k0 + lc);
        As[lc + 0][lr] = x4.x;
        As[lc + 1][lr] = x4.y;
        As[lc + 2][lr] = x4.z;
        As[lc + 3][lr] = x4.w;
        // W tile (coalesced float4)
        #pragma unroll
        for (int t = 0; t < 4; t++) {
            int f4 = tid + t * 256;
            int rr = f4 >> 5;
            int cc = (f4 & 31) << 2;
            *(float4*)&Bs[rr][cc] = *(const float4*)(W + (size_t)(k0 + rr) * EE + cc);
        }
        __syncthreads();

        #pragma unroll
        for (int kk = 0; kk < 32; kk++) {
            float4 a4 = *(const float4*)&As[kk][ty << 2];
            float4 b4 = *(const float4*)&Bs[kk][tx << 2];
            acc[0][0] = fmaf(a4.x, b4.x, acc[0][0]);
            acc[0][1] = fmaf(a4.x, b4.y, acc[0][1]);
            acc[0][2] = fmaf(a4.x, b4.z, acc[0][2]);
            acc[0][3] = fmaf(a4.x, b4.w, acc[0][3]);
            acc[1][0] = fmaf(a4.y, b4.x, acc[1][0]);
            acc[1][1] = fmaf(a4.y, b4.y, acc[1][1]);
            acc[1][2] = fmaf(a4.y, b4.z, acc[1][2]);
            acc[1][3] = fmaf(a4.y, b4.w, acc[1][3]);
            acc[2][0] = fmaf(a4.z, b4.x, acc[2][0]);
            acc[2][1] = fmaf(a4.z, b4.y, acc[2][1]);
            acc[2][2] = fmaf(a4.z, b4.z, acc[2][2]);
            acc[2][3] = fmaf(a4.z, b4.w, acc[2][3]);
            acc[3][0] = fmaf(a4.w, b4.x, acc[3][0]);
            acc[3][1] = fmaf(a4.w, b4.y, acc[3][1]);
            acc[3][2] = fmaf(a4.w, b4.z, acc[3][2]);
            acc[3][3] = fmaf(a4.w, b4.w, acc[3][3]);
        }
        __syncthreads();
    }

    #pragma unroll
    for (int i = 0; i < 4; i++) {
        float4 o = make_float4(acc[i][0], acc[i][1], acc[i][2], acc[i][3]);
        *(float4*)(O + (size_t)(m0 + (ty << 2) + i) * EE + (tx << 2)) = o;
    }
}

// ---------------------------------------------------------------------------
// Attention kernel: one block handles (b, 8 consecutive l rows).
// Phase 1: scores s[l][q] = sum_e tanh(qp[q][e] + kp[l][e]) * vc[e]
// Phase 2: per-l softmax over q (one warp per l)
// Phase 3: context[l][d] = sum_q a[l][q] * value[q][d]
// ---------------------------------------------------------------------------
__global__ __launch_bounds__(256, 2) void atten_kernel(
    const float* __restrict__ value, const float* __restrict__ vc,
    float* __restrict__ ctx_out, float* __restrict__ att_out)
{
    __shared__ float kv[TL][EE];       // 4 KB
    __shared__ float vcs[EE];          // 0.5 KB
    __shared__ float sraw[TL][LQ];     // 16 KB
    __shared__ float at[LQ][12];       // 24 KB (pad 12 -> 48B rows, 16B aligned)

    const int tid = threadIdx.x;
    const int b   = blockIdx.y;
    const int l0  = blockIdx.x * TL;

    const float* kp = g_kproj + (size_t)(b * LK + l0) * EE;
    const float* qp = g_qproj + (size_t)b * LQ * EE;

    for (int i = tid; i < TL * EE; i += 256) kv[i >> 7][i & 127] = kp[i];
    if (tid < EE) vcs[tid] = vc[tid];
    __syncthreads();

    // ---- Phase 1: each thread owns q = tid and q = tid+256 ----
    float acc0[TL] = {}, acc1[TL] = {};
    const float* q0p = qp + (size_t)tid * EE;
    const float* q1p = qp + (size_t)(tid + 256) * EE;

    #pragma unroll 2
    for (int e = 0; e < EE; e += 4) {
        float4 v4 = *(const float4*)(vcs + e);
        float4 qa = *(const float4*)(q0p + e);
        float4 qb = *(const float4*)(q1p + e);
        #pragma unroll
        for (int l = 0; l < TL; l++) {
            float4 k4 = *(const float4*)&kv[l][e];
            acc0[l] = fmaf(tanh_fast(qa.x + k4.x), v4.x, acc0[l]);
            acc0[l] = fmaf(tanh_fast(qa.y + k4.y), v4.y, acc0[l]);
            acc0[l] = fmaf(tanh_fast(qa.z + k4.z), v4.z, acc0[l]);
            acc0[l] = fmaf(tanh_fast(qa.w + k4.w), v4.w, acc0[l]);
            acc1[l] = fmaf(tanh_fast(qb.x + k4.x), v4.x, acc1[l]);
            acc1[l] = fmaf(tanh_fast(qb.y + k4.y), v4.y, acc1[l]);
            acc1[l] = fmaf(tanh_fast(qb.z + k4.z), v4.z, acc1[l]);
            acc1[l] = fmaf(tanh_fast(qb.w + k4.w), v4.w, acc1[l]);
        }
    }

    #pragma unroll
    for (int l = 0; l < TL; l++) {
        sraw[l][tid]       = acc0[l];
        sraw[l][tid + 256] = acc1[l];
    }
    __syncthreads();

    // ---- Phase 2: warp w does softmax for l = w over 512 q-values ----
    const int w = tid >> 5, lane = tid & 31;
    float vals[16];
    float mx = -1e30f;
    #pragma unroll
    for (int i = 0; i < 16; i++) {
        vals[i] = sraw[w][lane + 32 * i];
        mx = fmaxf(mx, vals[i]);
    }
    #pragma unroll
    for (int off = 16; off > 0; off >>= 1)
        mx = fmaxf(mx, __shfl_xor_sync(0xffffffffu, mx, off));
    float sum = 0.f;
    #pragma unroll
    for (int i = 0; i < 16; i++) {
        vals[i] = __expf(vals[i] - mx);
        sum += vals[i];
    }
    #pragma unroll
    for (int off = 16; off > 0; off >>= 1)
        sum += __shfl_xor_sync(0xffffffffu, sum, off);
    const float inv = 1.0f / sum;

    float* ap = att_out + (size_t)(b * LK + l0 + w) * LQ;
    #pragma unroll
    for (int i = 0; i < 16; i++) {
        float a = vals[i] * inv;
        int q = lane + 32 * i;
        ap[q]    = a;       // coalesced global atten write
        at[q][w] = a;       // transposed smem copy for phase 3
    }
    __syncthreads();

    // ---- Phase 3: thread owns d = tid; 8 context accumulators ----
    float c[TL] = {};
    const float* vp = value + (size_t)b * LQ * DD + tid;
    #pragma unroll 4
    for (int q = 0; q < LQ; q++) {
        float v = vp[(size_t)q * DD];                   // coalesced
        float4 a0 = *(const float4*)&at[q][0];          // broadcast
        float4 a1 = *(const float4*)&at[q][4];          // broadcast
        c[0] = fmaf(a0.x, v, c[0]);
        c[1] = fmaf(a0.y, v, c[1]);
        c[2] = fmaf(a0.z, v, c[2]);
        c[3] = fmaf(a0.w, v, c[3]);
        c[4] = fmaf(a1.x, v, c[4]);
        c[5] = fmaf(a1.y, v, c[5]);
        c[6] = fmaf(a1.z, v, c[6]);
        c[7] = fmaf(a1.w, v, c[7]);
    }
    float* cp = ctx_out + (size_t)(b * LK + l0) * DD + tid;
    #pragma unroll
    for (int l = 0; l < TL; l++) cp[(size_t)l * DD] = c[l];
}

extern "C" void kernel_launch(void* const* d_in, const int* in_sizes, int n_in,
                              void* d_out, int out_size)
{
    const float* query = (const float*)d_in[0];
    const float* key   = (const float*)d_in[1];
    const float* value = (const float*)d_in[2];
    const float* Wc1   = (const float*)d_in[3];
    const float* Wc2   = (const float*)d_in[4];
    const float* vc    = (const float*)d_in[5];

    float* ctx = (float*)d_out;                                  // [B, Lk, D]
    float* att = (float*)d_out + (size_t)BB * LK * DD;           // [B, Lk, Lq]

    proj_kernel<<<dim3((BB * LQ) / 32, 1, 2), 256>>>(query, key, Wc1, Wc2);
    atten_kernel<<<dim3(LK / TL, BB), 256>>>(value, vc, ctx, att);
}

// round 9
// speedup vs baseline: 1.0088x; 1.0088x over previous
#include <cuda_runtime.h>

#define BB 4
#define LQ 512
#define LK 512
#define EE 128
#define DD 256
#define TL 8

// Scratch (allocation-free: device globals).
// q projection stored TRANSPOSED: g_qprojT[b][e][q]  (e-major, q contiguous)
__device__ float g_qprojT[BB * EE * LQ];
__device__ float g_kproj[BB * LK * EE];

__device__ __forceinline__ float tanh_fast(float x) {
    float y;
    asm("tanh.approx.f32 %0, %1;" : "=f"(y) : "f"(x));
    return y;
}

// ---------------------------------------------------------------------------
// Projection GEMM: O[2048,128] = X[2048,256] @ W[256,128]
// blockIdx.z = 0 -> (query, Wc1) -> g_qprojT (transposed store via smem)
// blockIdx.z = 1 -> (key,   Wc2) -> g_kproj  (row-major store)
// BM=32, BN=128, BK=32; 256 threads; 4x4 outputs per thread.
// ---------------------------------------------------------------------------
__global__ __launch_bounds__(256) void proj_kernel(
    const float* __restrict__ query, const float* __restrict__ key,
    const float* __restrict__ Wc1, const float* __restrict__ Wc2)
{
    const float* X = (blockIdx.z == 0) ? query : key;
    const float* W = (blockIdx.z == 0) ? Wc1 : Wc2;

    __shared__ float As[32][36];    // [k][m]
    __shared__ float Bs[32][128];   // [k][n]
    __shared__ float Os[32][129];   // output staging for transposed store

    const int tid = threadIdx.x;
    const int m0  = blockIdx.x * 32;
    const int tx  = tid & 31;   // n-group (4 cols each)
    const int ty  = tid >> 5;   // m-group (4 rows each)

    const int lr = tid >> 3;          // 0..31 : m row for X load
    const int lc = (tid & 7) << 2;    // 0..28 : k col (float4)

    float acc[4][4] = {};

    for (int k0 = 0; k0 < DD; k0 += 32) {
        float4 x4 = *(const float4*)(X + (size_t)(m0 + lr) * DD + k0 + lc);
        As[lc + 0][lr] = x4.x;
        As[lc + 1][lr] = x4.y;
        As[lc + 2][lr] = x4.z;
        As[lc + 3][lr] = x4.w;
        #pragma unroll
        for (int t = 0; t < 4; t++) {
            int f4 = tid + t * 256;
            int rr = f4 >> 5;
            int cc = (f4 & 31) << 2;
            *(float4*)&Bs[rr][cc] = *(const float4*)(W + (size_t)(k0 + rr) * EE + cc);
        }
        __syncthreads();

        #pragma unroll
        for (int kk = 0; kk < 32; kk++) {
            float4 a4 = *(const float4*)&As[kk][ty << 2];
            float4 b4 = *(const float4*)&Bs[kk][tx << 2];
            acc[0][0] = fmaf(a4.x, b4.x, acc[0][0]);
            acc[0][1] = fmaf(a4.x, b4.y, acc[0][1]);
            acc[0][2] = fmaf(a4.x, b4.z, acc[0][2]);
            acc[0][3] = fmaf(a4.x, b4.w, acc[0][3]);
            acc[1][0] = fmaf(a4.y, b4.x, acc[1][0]);
            acc[1][1] = fmaf(a4.y, b4.y, acc[1][1]);
            acc[1][2] = fmaf(a4.y, b4.z, acc[1][2]);
            acc[1][3] = fmaf(a4.y, b4.w, acc[1][3]);
            acc[2][0] = fmaf(a4.z, b4.x, acc[2][0]);
            acc[2][1] = fmaf(a4.z, b4.y, acc[2][1]);
            acc[2][2] = fmaf(a4.z, b4.z, acc[2][2]);
            acc[2][3] = fmaf(a4.z, b4.w, acc[2][3]);
            acc[3][0] = fmaf(a4.w, b4.x, acc[3][0]);
            acc[3][1] = fmaf(a4.w, b4.y, acc[3][1]);
            acc[3][2] = fmaf(a4.w, b4.z, acc[3][2]);
            acc[3][3] = fmaf(a4.w, b4.w, acc[3][3]);
        }
        __syncthreads();
    }

    if (blockIdx.z == 0) {
        // Stage tile in smem, store transposed: g_qprojT[b][e][q] coalesced.
        #pragma unroll
        for (int i = 0; i < 4; i++) {
            Os[(ty << 2) + i][(tx << 2) + 0] = acc[i][0];
            Os[(ty << 2) + i][(tx << 2) + 1] = acc[i][1];
            Os[(ty << 2) + i][(tx << 2) + 2] = acc[i][2];
            Os[(ty << 2) + i][(tx << 2) + 3] = acc[i][3];
        }
        __syncthreads();
        const int b    = m0 >> 9;         // 512 rows per batch, tile never straddles
        const int q0   = m0 & 511;
        const int lane = tid & 31;
        const int w    = tid >> 5;
        #pragma unroll
        for (int r = 0; r < 16; r++) {
            int e = w * 16 + r;
            g_qprojT[((size_t)b * EE + e) * LQ + q0 + lane] = Os[lane][e];
        }
    } else {
        #pragma unroll
        for (int i = 0; i < 4; i++) {
            float4 o = make_float4(acc[i][0], acc[i][1], acc[i][2], acc[i][3]);
            *(float4*)(g_kproj + (size_t)(m0 + (ty << 2) + i) * EE + (tx << 2)) = o;
        }
    }
}

// ---------------------------------------------------------------------------
// Attention kernel: one block = (b, 8 consecutive l rows).
// Phase 1: scores s[l][q] = sum_e tanh(qT[e][q] + kT[e][l]) * vc[e]
//          (q loads now warp-coalesced LDG.64; k via broadcast LDS.128)
// Phase 2: per-l softmax over q (one warp per l)
// Phase 3: context[l][d] = sum_q a[l][q] * value[q][d]
// ---------------------------------------------------------------------------
__global__ __launch_bounds__(256, 2) void atten_kernel(
    const float* __restrict__ value, const float* __restrict__ vc,
    float* __restrict__ ctx_out, float* __restrict__ att_out)
{
    __shared__ float kvT[EE][TL];      // 4 KB, transposed k tile: kvT[e][l]
    __shared__ float vcs[EE];          // 0.5 KB
    __shared__ float sraw[TL][LQ];     // 16 KB
    __shared__ float at[LQ][12];       // 24 KB (pad 12: 48B rows, 16B aligned)

    const int tid = threadIdx.x;
    const int b   = blockIdx.y;
    const int l0  = blockIdx.x * TL;

    const float* kp = g_kproj + (size_t)(b * LK + l0) * EE;
    for (int i = tid; i < TL * EE; i += 256) {
        int l = i >> 7, e = i & 127;
        kvT[e][l] = kp[i];
    }
    if (tid < EE) vcs[tid] = vc[tid];
    __syncthreads();

    // ---- Phase 1: each thread owns q = 2*tid and q = 2*tid+1 ----
    const float* qT = g_qprojT + (size_t)b * EE * LQ;
    const int q0 = tid << 1;

    float acc0[TL] = {}, acc1[TL] = {};

    #pragma unroll 2
    for (int e = 0; e < EE; e++) {
        float2 q2 = *(const float2*)(qT + (size_t)e * LQ + q0);   // coalesced
        float  v  = vcs[e];                                        // broadcast
        float4 ka = *(const float4*)&kvT[e][0];                    // broadcast
        float4 kb = *(const float4*)&kvT[e][4];                    // broadcast
        acc0[0] = fmaf(tanh_fast(q2.x + ka.x), v, acc0[0]);
        acc0[1] = fmaf(tanh_fast(q2.x + ka.y), v, acc0[1]);
        acc0[2] = fmaf(tanh_fast(q2.x + ka.z), v, acc0[2]);
        acc0[3] = fmaf(tanh_fast(q2.x + ka.w), v, acc0[3]);
        acc0[4] = fmaf(tanh_fast(q2.x + kb.x), v, acc0[4]);
        acc0[5] = fmaf(tanh_fast(q2.x + kb.y), v, acc0[5]);
        acc0[6] = fmaf(tanh_fast(q2.x + kb.z), v, acc0[6]);
        acc0[7] = fmaf(tanh_fast(q2.x + kb.w), v, acc0[7]);
        acc1[0] = fmaf(tanh_fast(q2.y + ka.x), v, acc1[0]);
        acc1[1] = fmaf(tanh_fast(q2.y + ka.y), v, acc1[1]);
        acc1[2] = fmaf(tanh_fast(q2.y + ka.z), v, acc1[2]);
        acc1[3] = fmaf(tanh_fast(q2.y + ka.w), v, acc1[3]);
        acc1[4] = fmaf(tanh_fast(q2.y + kb.x), v, acc1[4]);
        acc1[5] = fmaf(tanh_fast(q2.y + kb.y), v, acc1[5]);
        acc1[6] = fmaf(tanh_fast(q2.y + kb.z), v, acc1[6]);
        acc1[7] = fmaf(tanh_fast(q2.y + kb.w), v, acc1[7]);
    }

    #pragma unroll
    for (int l = 0; l < TL; l++) {
        float2 s2 = make_float2(acc0[l], acc1[l]);
        *(float2*)&sraw[l][q0] = s2;
    }
    __syncthreads();

    // ---- Phase 2: warp w does softmax for l = w over 512 q-values ----
    const int w = tid >> 5, lane = tid & 31;
    float vals[16];
    float mx = -1e30f;
    #pragma unroll
    for (int i = 0; i < 16; i++) {
        vals[i] = sraw[w][lane + 32 * i];
        mx = fmaxf(mx, vals[i]);
    }
    #pragma unroll
    for (int off = 16; off > 0; off >>= 1)
        mx = fmaxf(mx, __shfl_xor_sync(0xffffffffu, mx, off));
    float sum = 0.f;
    #pragma unroll
    for (int i = 0; i < 16; i++) {
        vals[i] = __expf(vals[i] - mx);
        sum += vals[i];
    }
    #pragma unroll
    for (int off = 16; off > 0; off >>= 1)
        sum += __shfl_xor_sync(0xffffffffu, sum, off);
    const float inv = 1.0f / sum;

    float* ap = att_out + (size_t)(b * LK + l0 + w) * LQ;
    #pragma unroll
    for (int i = 0; i < 16; i++) {
        float a = vals[i] * inv;
        int q = lane + 32 * i;
        ap[q]    = a;       // coalesced global atten write
        at[q][w] = a;       // transposed smem copy for phase 3
    }
    __syncthreads();

    // ---- Phase 3: thread owns d = tid; 8 context accumulators ----
    float c[TL] = {};
    const float* vp = value + (size_t)b * LQ * DD + tid;
    #pragma unroll 4
    for (int q = 0; q < LQ; q++) {
        float v = vp[(size_t)q * DD];                   // coalesced
        float4 a0 = *(const float4*)&at[q][0];          // broadcast
        float4 a1 = *(const float4*)&at[q][4];          // broadcast
        c[0] = fmaf(a0.x, v, c[0]);
        c[1] = fmaf(a0.y, v, c[1]);
        c[2] = fmaf(a0.z, v, c[2]);
        c[3] = fmaf(a0.w, v, c[3]);
        c[4] = fmaf(a1.x, v, c[4]);
        c[5] = fmaf(a1.y, v, c[5]);
        c[6] = fmaf(a1.z, v, c[6]);
        c[7] = fmaf(a1.w, v, c[7]);
    }
    float* cp = ctx_out + (size_t)(b * LK + l0) * DD + tid;
    #pragma unroll
    for (int l = 0; l < TL; l++) cp[(size_t)l * DD] = c[l];
}

extern "C" void kernel_launch(void* const* d_in, const int* in_sizes, int n_in,
                              void* d_out, int out_size)
{
    const float* query = (const float*)d_in[0];
    const float* key   = (const float*)d_in[1];
    const float* value = (const float*)d_in[2];
    const float* Wc1   = (const float*)d_in[3];
    const float* Wc2   = (const float*)d_in[4];
    const float* vc    = (const float*)d_in[5];

    float* ctx = (float*)d_out;                                  // [B, Lk, D]
    float* att = (float*)d_out + (size_t)BB * LK * DD;           // [B, Lk, Lq]

    proj_kernel<<<dim3((BB * LQ) / 32, 1, 2), 256>>>(query, key, Wc1, Wc2);
    atten_kernel<<<dim3(LK / TL, BB), 256>>>(value, vc, ctx, att);
}